// round 2
// baseline (speedup 1.0000x reference)
#include <cuda_runtime.h>
#include <math.h>

#define EMBED   192
#define NHEADS  8
#define HDIM    24
#define HDIM2   12            // HDIM/2 float2 pairs
#define BATCH   32
#define SEQ     1024
#define MROWS   (BATCH * SEQ)   // 32768

typedef unsigned long long ull;

// Scratch (no allocations allowed; module globals are fine)
__device__ float g_qkv[(size_t)MROWS * 3 * EMBED];   // [32768, 576]  Q|K|V packed per row
__device__ float g_attn[(size_t)MROWS * EMBED];      // [32768, 192]  attention output [b,n,h,d]

// ---- packed f32x2 helpers (FFMA2 path; only reachable via PTX) -------------
__device__ __forceinline__ ull pack2(float lo, float hi) {
    ull r; asm("mov.b64 %0, {%1, %2};" : "=l"(r) : "f"(lo), "f"(hi)); return r;
}
__device__ __forceinline__ float2 unpack2(ull v) {
    float2 f; asm("mov.b64 {%0, %1}, %2;" : "=f"(f.x), "=f"(f.y) : "l"(v)); return f;
}
__device__ __forceinline__ void fma2(ull& d, ull a, ull b) {
    asm("fma.rn.f32x2 %0, %1, %2, %0;" : "+l"(d) : "l"(a), "l"(b));
}
__device__ __forceinline__ void mul2(ull& d, ull a) {
    asm("mul.rn.f32x2 %0, %0, %1;" : "+l"(d) : "l"(a));
}

// ---------------------------------------------------------------------------
// GEMM: C[M,N] = A[M,K] @ B[K,N] + bias[N]
// BM=128, BN=64, BK=16, 256 threads, 8x4 microtile (m paired for f32x2).
// As stored transposed [BK][BM] so the a-vector is a contiguous LDS.128 pair.
// All dims exact multiples of tiles (M%128==0, N%64==0, K%16==0).
// ---------------------------------------------------------------------------
__global__ __launch_bounds__(256)
void gemm_bias_kernel(const float* __restrict__ A, const float* __restrict__ Bm,
                      const float* __restrict__ bias, float* __restrict__ C,
                      int M, int Nn, int K) {
    constexpr int BM = 128, BN = 64, BK = 16;
    __shared__ float Ast[BK][BM + 4];   // transposed A; pad keeps float4 alignment (132%4==0)
    __shared__ float Bs[BK][BN];

    const int tid = threadIdx.x;
    const int tx = tid & 15;            // n: 16 cols * 4
    const int ty = tid >> 4;            // m: 16 rows * 8
    const int rowBase = blockIdx.y * BM;
    const int colBase = blockIdx.x * BN;

    ull acc2[4][4];                     // [m-pair][n] : (row 2m2, row 2m2+1)
    #pragma unroll
    for (int i = 0; i < 4; i++)
        #pragma unroll
        for (int j = 0; j < 4; j++) acc2[i][j] = 0ull;

    for (int k0 = 0; k0 < K; k0 += BK) {
        // A tile 128x16, transposed into smem
        #pragma unroll
        for (int i = 0; i < (BM * BK) / 256; i++) {
            int li = tid + i * 256;
            int r = li >> 4, c = li & 15;               // coalesced on c
            Ast[c][r] = A[(size_t)(rowBase + r) * K + (k0 + c)];
        }
        // B tile 16x64
        #pragma unroll
        for (int i = 0; i < (BK * BN) / 256; i++) {
            int li = tid + i * 256;
            int r = li >> 6, c = li & 63;               // coalesced on c
            Bs[r][c] = Bm[(size_t)(k0 + r) * Nn + (colBase + c)];
        }
        __syncthreads();

        #pragma unroll
        for (int kk = 0; kk < BK; kk++) {
            float4 a0 = *(const float4*)&Ast[kk][ty * 8];
            float4 a1 = *(const float4*)&Ast[kk][ty * 8 + 4];
            float4 bv = *(const float4*)&Bs[kk][tx * 4];
            ull a2[4] = { pack2(a0.x, a0.y), pack2(a0.z, a0.w),
                          pack2(a1.x, a1.y), pack2(a1.z, a1.w) };
            ull bd[4] = { pack2(bv.x, bv.x), pack2(bv.y, bv.y),
                          pack2(bv.z, bv.z), pack2(bv.w, bv.w) };
            #pragma unroll
            for (int m2 = 0; m2 < 4; m2++)
                #pragma unroll
                for (int n = 0; n < 4; n++)
                    fma2(acc2[m2][n], a2[m2], bd[n]);
        }
        __syncthreads();
    }

    #pragma unroll
    for (int m2 = 0; m2 < 4; m2++) {
        int gm0 = rowBase + ty * 8 + m2 * 2;
        #pragma unroll
        for (int n = 0; n < 4; n++) {
            int gn = colBase + tx * 4 + n;
            float2 v = unpack2(acc2[m2][n]);
            float bi = bias[gn];
            C[(size_t)gm0 * Nn + gn]       = v.x + bi;
            C[(size_t)(gm0 + 1) * Nn + gn] = v.y + bi;
        }
    }
}

// ---------------------------------------------------------------------------
// Flash attention with packed f32x2: one block per (b, h, q-tile of 128),
// one query per thread. K/V staged in smem as float2 pairs; online softmax
// in log2 domain.
// ---------------------------------------------------------------------------
__global__ __launch_bounds__(128)
void attn_kernel() {
    const int qt  = blockIdx.x & 7;
    const int bh  = blockIdx.x >> 3;
    const int b   = bh >> 3;
    const int h   = bh & 7;
    const int tid = threadIdx.x;
    const int row = qt * 128 + tid;

    const float scale = 1.44269504088896340736f * rsqrtf((float)HDIM);

    // q, pre-scaled, as 12 packed pairs
    ull q2[HDIM2];
    {
        const float* qptr = g_qkv + ((size_t)(b * SEQ + row)) * (3 * EMBED) + h * HDIM;
        #pragma unroll
        for (int d2 = 0; d2 < HDIM2; d2++)
            q2[d2] = pack2(qptr[2 * d2] * scale, qptr[2 * d2 + 1] * scale);
    }

    float m = -INFINITY, l = 0.f;
    ull o2[HDIM2];
    #pragma unroll
    for (int d2 = 0; d2 < HDIM2; d2++) o2[d2] = 0ull;

    __shared__ ull Ks2[32 * HDIM2];
    __shared__ ull Vs2[32 * HDIM2];

    for (int kc = 0; kc < SEQ / 32; kc++) {
        const int j0 = kc * 32;
        __syncthreads();
        #pragma unroll
        for (int it = 0; it < 3; it++) {                 // 384 pairs / 128 threads
            int i = tid + it * 128;
            int j = i / HDIM2, d2 = i % HDIM2;
            size_t fidx = ((size_t)(b * SEQ + j0 + j)) * (3 * EMBED) + h * HDIM + 2 * d2;
            Ks2[i] = *(const ull*)(g_qkv + fidx + EMBED);
            Vs2[i] = *(const ull*)(g_qkv + fidx + 2 * EMBED);
        }
        __syncthreads();

        float s[32];
        float cmax = -INFINITY;
        #pragma unroll
        for (int j = 0; j < 32; j++) {
            ull acc = 0ull;
            #pragma unroll
            for (int d2 = 0; d2 < HDIM2; d2++)
                fma2(acc, q2[d2], Ks2[j * HDIM2 + d2]);
            float2 ac = unpack2(acc);
            s[j] = ac.x + ac.y;
            cmax = fmaxf(cmax, s[j]);
        }

        const float mnew = fmaxf(m, cmax);
        const float corr = exp2f(m - mnew);              // first iter: exp2(-inf)=0
        l *= corr;
        const ull corr2 = pack2(corr, corr);
        #pragma unroll
        for (int d2 = 0; d2 < HDIM2; d2++) mul2(o2[d2], corr2);

        #pragma unroll
        for (int j = 0; j < 32; j++) {
            const float p = exp2f(s[j] - mnew);
            l += p;
            const ull p2 = pack2(p, p);
            #pragma unroll
            for (int d2 = 0; d2 < HDIM2; d2++)
                fma2(o2[d2], p2, Vs2[j * HDIM2 + d2]);
        }
        m = mnew;
    }

    const float inv = 1.f / l;
    float* optr = g_attn + ((size_t)(b * SEQ + row)) * EMBED + h * HDIM;
    #pragma unroll
    for (int d2 = 0; d2 < HDIM2; d2++) {
        float2 v = unpack2(o2[d2]);
        optr[2 * d2]     = v.x * inv;
        optr[2 * d2 + 1] = v.y * inv;
    }
}

// ---------------------------------------------------------------------------
extern "C" void kernel_launch(void* const* d_in, const int* in_sizes, int n_in,
                              void* d_out, int out_size) {
    const float* x     = (const float*)d_in[0];   // [32, 1024, 192]
    const float* Wqkv  = (const float*)d_in[1];   // [192, 576]
    const float* bqkv  = (const float*)d_in[2];   // [576]
    const float* Wproj = (const float*)d_in[3];   // [192, 192]
    const float* bproj = (const float*)d_in[4];   // [192]
    float* out = (float*)d_out;                   // [32, 1024, 192]

    float *qkv_ptr, *attn_ptr;
    cudaGetSymbolAddress((void**)&qkv_ptr,  g_qkv);
    cudaGetSymbolAddress((void**)&attn_ptr, g_attn);

    // 1) QKV projection: [32768,192] @ [192,576] + b
    {
        dim3 grid(3 * EMBED / 64, MROWS / 128);
        gemm_bias_kernel<<<grid, 256>>>(x, Wqkv, bqkv, qkv_ptr, MROWS, 3 * EMBED, EMBED);
    }
    // 2) Attention
    attn_kernel<<<BATCH * NHEADS * (SEQ / 128), 128>>>();
    // 3) Output projection: [32768,192] @ [192,192] + b
    {
        dim3 grid(EMBED / 64, MROWS / 128);
        gemm_bias_kernel<<<grid, 256>>>(attn_ptr, Wproj, bproj, out, MROWS, EMBED, EMBED);
    }
}

// round 3
// speedup vs baseline: 2.1528x; 2.1528x over previous
#include <cuda_runtime.h>
#include <math.h>

#define EMBED   192
#define NHEADS  8
#define HDIM    24
#define BATCH   32
#define SEQ     1024
#define MROWS   (BATCH * SEQ)   // 32768

// Scratch (module globals; no allocation allowed)
__device__ float g_qkv[(size_t)MROWS * 3 * EMBED];   // [32768, 576] Q|K|V per row
__device__ float g_attn[(size_t)MROWS * EMBED];      // [32768, 192] attn out [b,n,h,d]

// ---------------------------------------------------------------------------
// R1 scalar GEMM (known good): C[M,N] = A[M,K] @ B[K,N] + bias[N]
// ---------------------------------------------------------------------------
__global__ __launch_bounds__(256)
void gemm_bias_kernel(const float* __restrict__ A, const float* __restrict__ Bm,
                      const float* __restrict__ bias, float* __restrict__ C,
                      int M, int Nn, int K) {
    constexpr int BM = 64, BN = 64, BK = 16;
    __shared__ float As[BM][BK + 1];
    __shared__ float Bs[BK][BN];

    const int tid = threadIdx.x;
    const int tx = tid & 15;
    const int ty = tid >> 4;
    const int rowBase = blockIdx.y * BM;
    const int colBase = blockIdx.x * BN;

    float acc[4][4] = {};

    for (int k0 = 0; k0 < K; k0 += BK) {
        #pragma unroll
        for (int i = 0; i < (BM * BK) / 256; i++) {
            int li = tid + i * 256;
            int r = li / BK, c = li % BK;
            As[r][c] = A[(size_t)(rowBase + r) * K + (k0 + c)];
        }
        #pragma unroll
        for (int i = 0; i < (BK * BN) / 256; i++) {
            int li = tid + i * 256;
            int r = li / BN, c = li % BN;
            Bs[r][c] = Bm[(size_t)(k0 + r) * Nn + (colBase + c)];
        }
        __syncthreads();

        #pragma unroll
        for (int kk = 0; kk < BK; kk++) {
            float a[4], b[4];
            #pragma unroll
            for (int m = 0; m < 4; m++) a[m] = As[ty * 4 + m][kk];
            #pragma unroll
            for (int n = 0; n < 4; n++) b[n] = Bs[kk][tx * 4 + n];
            #pragma unroll
            for (int m = 0; m < 4; m++)
                #pragma unroll
                for (int n = 0; n < 4; n++)
                    acc[m][n] += a[m] * b[n];
        }
        __syncthreads();
    }

    #pragma unroll
    for (int m = 0; m < 4; m++) {
        int gm = rowBase + ty * 4 + m;
        #pragma unroll
        for (int n = 0; n < 4; n++) {
            int gn = colBase + tx * 4 + n;
            C[(size_t)gm * Nn + gn] = acc[m][n] + bias[gn];
        }
    }
}

// ---------------------------------------------------------------------------
// tf32 mma helpers
// ---------------------------------------------------------------------------
__device__ __forceinline__ unsigned cvt_tf32(float x) {
    unsigned r; asm("cvt.rna.tf32.f32 %0, %1;" : "=r"(r) : "f"(x)); return r;
}
__device__ __forceinline__ void mma_tf32(float c[4], const unsigned a[4], const unsigned b[2]) {
    asm("mma.sync.aligned.m16n8k8.row.col.f32.tf32.tf32.f32 "
        "{%0,%1,%2,%3}, {%4,%5,%6,%7}, {%8,%9}, {%0,%1,%2,%3};"
        : "+f"(c[0]), "+f"(c[1]), "+f"(c[2]), "+f"(c[3])
        : "r"(a[0]), "r"(a[1]), "r"(a[2]), "r"(a[3]), "r"(b[0]), "r"(b[1]));
}

// ---------------------------------------------------------------------------
// Flash attention on tensor cores.
// Block: 4 warps; handles (b, h, q-tile of 64). Warp w owns 16 q rows.
// QK^T: 3xTF32 (full fp32-accurate logits). PV: single tf32 (err ~1e-4).
// Fragment maps (m16n8k8 tf32), g = lane>>2, t = lane&3:
//   A: a0=(g,t) a1=(g+8,t) a2=(g,t+4) a3=(g+8,t+4)
//   B: b0=(t,g) b1=(t+4,g)          C: c0=(g,2t) c1=(g,2t+1) c2/c3 = rows g+8
// ---------------------------------------------------------------------------
#define KTILE 64
#define KSTR  28   // K smem row stride: conflict-free for QK B-frag loads
#define VSTR  68   // V^T smem row stride: conflict-free for PV B-frag loads
#define PSTR  68

__global__ __launch_bounds__(128)
void attn_mma_kernel() {
    __shared__ unsigned Khi[KTILE * KSTR];
    __shared__ unsigned Klo[KTILE * KSTR];
    __shared__ unsigned Vt [HDIM * VSTR];        // V transposed: [d][key]
    __shared__ unsigned Ps [4 * 16 * PSTR];      // per-warp P tiles

    const int tid  = threadIdx.x;
    const int warp = tid >> 5, lane = tid & 31;
    const int g = lane >> 2, t = lane & 3;

    const int qt = blockIdx.x & 15;              // 16 q-tiles of 64
    const int bh = blockIdx.x >> 4;
    const int b  = bh >> 3, h = bh & 7;
    const int qbase = qt * 64 + warp * 16;

    const float scale = 1.44269504088896340736f * rsqrtf((float)HDIM);

    // ---- load Q fragments (hi/lo split), pre-scaled into log2 domain ----
    unsigned Ahi[3][4], Alo[3][4];
    {
        #pragma unroll
        for (int kc = 0; kc < 3; kc++) {
            #pragma unroll
            for (int rr = 0; rr < 2; rr++) {       // rows g, g+8
                int qrow = qbase + g + rr * 8;
                const float* qp = g_qkv + ((size_t)(b * SEQ + qrow)) * 576 + h * HDIM;
                #pragma unroll
                for (int cc = 0; cc < 2; cc++) {   // cols t, t+4
                    float v = qp[kc * 8 + t + cc * 4] * scale;
                    unsigned hib = cvt_tf32(v);
                    float hif = __uint_as_float(hib);
                    Ahi[kc][rr + cc * 2] = hib;
                    Alo[kc][rr + cc * 2] = cvt_tf32(v - hif);
                }
            }
        }
    }

    float m0 = -INFINITY, m1 = -INFINITY, l0 = 0.f, l1 = 0.f;
    float o[3][4];
    #pragma unroll
    for (int nd = 0; nd < 3; nd++)
        #pragma unroll
        for (int i = 0; i < 4; i++) o[nd][i] = 0.f;

    unsigned* Pw = Ps + warp * 16 * PSTR;

    for (int j0 = 0; j0 < SEQ; j0 += KTILE) {
        __syncthreads();
        // ---- cooperative K/V tile load: thread = (row=tid>>1, half=tid&1) ----
        {
            int row = tid >> 1, half = tid & 1;
            const float* base = g_qkv + ((size_t)(b * SEQ + j0 + row)) * 576
                                + h * HDIM + half * 12;
            #pragma unroll
            for (int i = 0; i < 3; i++) {
                float4 kv = *(const float4*)(base + EMBED + i * 4);       // K
                float4 vv = *(const float4*)(base + 2 * EMBED + i * 4);   // V
                float kf[4] = {kv.x, kv.y, kv.z, kv.w};
                float vf[4] = {vv.x, vv.y, vv.z, vv.w};
                #pragma unroll
                for (int c = 0; c < 4; c++) {
                    int d = half * 12 + i * 4 + c;
                    unsigned hib = cvt_tf32(kf[c]);
                    float hif = __uint_as_float(hib);
                    Khi[row * KSTR + d] = hib;
                    Klo[row * KSTR + d] = cvt_tf32(kf[c] - hif);
                    Vt[d * VSTR + row]  = cvt_tf32(vf[c]);
                }
            }
        }
        __syncthreads();

        // ---- S = Q K^T (3xTF32), 8 key-blocks of 8 ----
        float s[8][4];
        #pragma unroll
        for (int n = 0; n < 8; n++) {
            float c[4] = {0.f, 0.f, 0.f, 0.f};
            #pragma unroll
            for (int kc = 0; kc < 3; kc++) {
                int key = n * 8 + g;
                int d   = kc * 8 + t;
                unsigned bh2[2] = { Khi[key * KSTR + d], Khi[key * KSTR + d + 4] };
                unsigned bl2[2] = { Klo[key * KSTR + d], Klo[key * KSTR + d + 4] };
                mma_tf32(c, Ahi[kc], bh2);
                mma_tf32(c, Alo[kc], bh2);
                mma_tf32(c, Ahi[kc], bl2);
            }
            s[n][0] = c[0]; s[n][1] = c[1]; s[n][2] = c[2]; s[n][3] = c[3];
        }

        // ---- online softmax (rows g -> m0/l0, g+8 -> m1/l1) ----
        float tm0 = -INFINITY, tm1 = -INFINITY;
        #pragma unroll
        for (int n = 0; n < 8; n++) {
            tm0 = fmaxf(tm0, fmaxf(s[n][0], s[n][1]));
            tm1 = fmaxf(tm1, fmaxf(s[n][2], s[n][3]));
        }
        #pragma unroll
        for (int off = 1; off < 4; off <<= 1) {
            tm0 = fmaxf(tm0, __shfl_xor_sync(0xffffffffu, tm0, off));
            tm1 = fmaxf(tm1, __shfl_xor_sync(0xffffffffu, tm1, off));
        }
        float mn0 = fmaxf(m0, tm0), mn1 = fmaxf(m1, tm1);
        float corr0 = exp2f(m0 - mn0), corr1 = exp2f(m1 - mn1);  // first iter: 0
        l0 *= corr0; l1 *= corr1;
        #pragma unroll
        for (int nd = 0; nd < 3; nd++) {
            o[nd][0] *= corr0; o[nd][1] *= corr0;
            o[nd][2] *= corr1; o[nd][3] *= corr1;
        }

        float ls0 = 0.f, ls1 = 0.f;
        #pragma unroll
        for (int n = 0; n < 8; n++) {
            float p0 = exp2f(s[n][0] - mn0);
            float p1 = exp2f(s[n][1] - mn0);
            float p2 = exp2f(s[n][2] - mn1);
            float p3 = exp2f(s[n][3] - mn1);
            ls0 += p0 + p1; ls1 += p2 + p3;
            Pw[g * PSTR + n * 8 + 2 * t]           = cvt_tf32(p0);
            Pw[g * PSTR + n * 8 + 2 * t + 1]       = cvt_tf32(p1);
            Pw[(g + 8) * PSTR + n * 8 + 2 * t]     = cvt_tf32(p2);
            Pw[(g + 8) * PSTR + n * 8 + 2 * t + 1] = cvt_tf32(p3);
        }
        #pragma unroll
        for (int off = 1; off < 4; off <<= 1) {
            ls0 += __shfl_xor_sync(0xffffffffu, ls0, off);
            ls1 += __shfl_xor_sync(0xffffffffu, ls1, off);
        }
        l0 += ls0; l1 += ls1;
        m0 = mn0; m1 = mn1;
        __syncwarp();

        // ---- O += P V  (single tf32) ----
        #pragma unroll
        for (int kc = 0; kc < 8; kc++) {
            unsigned a[4];
            a[0] = Pw[g * PSTR + kc * 8 + t];
            a[1] = Pw[(g + 8) * PSTR + kc * 8 + t];
            a[2] = Pw[g * PSTR + kc * 8 + t + 4];
            a[3] = Pw[(g + 8) * PSTR + kc * 8 + t + 4];
            #pragma unroll
            for (int nd = 0; nd < 3; nd++) {
                unsigned bb[2] = { Vt[(nd * 8 + g) * VSTR + kc * 8 + t],
                                   Vt[(nd * 8 + g) * VSTR + kc * 8 + t + 4] };
                // B fragment wants V^T[k][n]: b0=(k=t, n=g) -> Vt[n][k] transposed read
                mma_tf32(o[nd], a, bb);
            }
        }
    }

    // ---- epilogue ----
    float inv0 = 1.f / l0, inv1 = 1.f / l1;
    int qrow0 = qbase + g, qrow1 = qbase + g + 8;
    float* out0 = g_attn + ((size_t)(b * SEQ + qrow0)) * EMBED + h * HDIM;
    float* out1 = g_attn + ((size_t)(b * SEQ + qrow1)) * EMBED + h * HDIM;
    #pragma unroll
    for (int nd = 0; nd < 3; nd++) {
        int d0 = nd * 8 + 2 * t;
        out0[d0]     = o[nd][0] * inv0;
        out0[d0 + 1] = o[nd][1] * inv0;
        out1[d0]     = o[nd][2] * inv1;
        out1[d0 + 1] = o[nd][3] * inv1;
    }
}

// ---------------------------------------------------------------------------
extern "C" void kernel_launch(void* const* d_in, const int* in_sizes, int n_in,
                              void* d_out, int out_size) {
    const float* x     = (const float*)d_in[0];
    const float* Wqkv  = (const float*)d_in[1];
    const float* bqkv  = (const float*)d_in[2];
    const float* Wproj = (const float*)d_in[3];
    const float* bproj = (const float*)d_in[4];
    float* out = (float*)d_out;

    float *qkv_ptr, *attn_ptr;
    cudaGetSymbolAddress((void**)&qkv_ptr,  g_qkv);
    cudaGetSymbolAddress((void**)&attn_ptr, g_attn);

    // 1) QKV projection
    {
        dim3 grid(3 * EMBED / 64, MROWS / 64);
        gemm_bias_kernel<<<grid, 256>>>(x, Wqkv, bqkv, qkv_ptr, MROWS, 3 * EMBED, EMBED);
    }
    // 2) Attention (tensor cores): 256 bh pairs x 16 q-tiles
    attn_mma_kernel<<<BATCH * NHEADS * (SEQ / 64), 128>>>();
    // 3) Output projection
    {
        dim3 grid(EMBED / 64, MROWS / 64);
        gemm_bias_kernel<<<grid, 256>>>(attn_ptr, Wproj, bproj, out, MROWS, EMBED, EMBED);
    }
}